// round 2
// baseline (speedup 1.0000x reference)
#include <cuda_runtime.h>
#include <math.h>

#define Bb 8
#define Np 4096
#define Gg 128
#define Kk 16
#define Vv 64
#define Mm 64
#define Dd 384
#define NHh 8
#define DHh 48
#define FFf 1536

__device__ float g_centers[2][Bb*Gg*3];
__device__ int   g_nidx[Bb*Gg*Kk];
__device__ int   g_nidxS[Bb*Gg*Kk];
__device__ float g_rel[Bb*Gg*Kk*3];
__device__ float g_f1[Bb*Gg*Kk*128];
__device__ float g_f2[Bb*Gg*Kk*256];
__device__ float g_gmax[Bb*Gg*256];
__device__ float g_cat[Bb*Gg*Kk*512];
__device__ float g_t1[Bb*Gg*Kk*512];
__device__ float g_t2[Bb*Gg*Kk*Dd];
__device__ float g_tokens[2][Bb*Gg*Dd];
__device__ float g_cpe[2][Bb*Gg*Dd];
__device__ float g_ppe[2][Bb*Np*Dd];
__device__ unsigned char g_mfull[2][Bb*Gg*Gg];
__device__ unsigned char g_mvis[2][Bb*Vv*Vv];
__device__ float g_vis3[Bb*Vv*3];
__device__ float g_visbuf[2][Bb*Vv*Dd];
__device__ float g_fullbuf[2][Bb*Gg*Dd];
__device__ float g_decx[2][Bb*(Mm+Vv)*Dd];
__device__ float g_mbuf[Bb*Gg*Dd];
__device__ float g_lnm[Bb*Gg*Dd];
__device__ float g_lnS[Bb*Gg*Dd];
__device__ float g_lnT[Bb*Gg*Dd];
__device__ float g_lnbig[Bb*Np*Dd];
__device__ float g_qbuf[Bb*Np*Dd];
__device__ float g_kbuf[Bb*Gg*Dd];
__device__ float g_vbuf[Bb*Gg*Dd];
__device__ float g_ctx[Bb*Np*Dd];
__device__ float g_hid[Bb*Np*FFf];
__device__ float g_upcat[Bb*Np*387];
__device__ int   g_nn3i[Bb*Np*3];
__device__ float g_nn3w[Bb*Np*3];
__device__ float g_lpart[2*64];

// C[rows,Nc] = act(A[rows,Kd] @ W[Kd,Nc] + bias) (+= if accum). rows%64==0, Nc%64==0.
__global__ void gemm_kernel(const float* __restrict__ A, const float* __restrict__ W,
                            const float* __restrict__ bias, float* __restrict__ C,
                            int rows, int Kd, int Nc, int relu, int accum)
{
    __shared__ float As[16][64];
    __shared__ float Ws[16][64];
    int tid = threadIdx.x, tx = tid & 15, ty = tid >> 4;
    int row0 = blockIdx.y * 64, col0 = blockIdx.x * 64;
    float acc[4][4] = {};
    for (int k0 = 0; k0 < Kd; k0 += 16) {
        #pragma unroll
        for (int l = 0; l < 4; l++) {
            int idx = tid + l*256, m = idx >> 4, kk = idx & 15;
            As[kk][m] = (k0 + kk < Kd) ? A[(size_t)(row0+m)*Kd + k0 + kk] : 0.f;
        }
        #pragma unroll
        for (int l = 0; l < 4; l++) {
            int idx = tid + l*256, kk = idx >> 6, n = idx & 63;
            Ws[kk][n] = (k0 + kk < Kd) ? W[(size_t)(k0+kk)*Nc + col0 + n] : 0.f;
        }
        __syncthreads();
        #pragma unroll
        for (int kk = 0; kk < 16; kk++) {
            float a0=As[kk][ty*4],a1=As[kk][ty*4+1],a2=As[kk][ty*4+2],a3=As[kk][ty*4+3];
            float b0=Ws[kk][tx*4],b1=Ws[kk][tx*4+1],b2=Ws[kk][tx*4+2],b3=Ws[kk][tx*4+3];
            acc[0][0]+=a0*b0;acc[0][1]+=a0*b1;acc[0][2]+=a0*b2;acc[0][3]+=a0*b3;
            acc[1][0]+=a1*b0;acc[1][1]+=a1*b1;acc[1][2]+=a1*b2;acc[1][3]+=a1*b3;
            acc[2][0]+=a2*b0;acc[2][1]+=a2*b1;acc[2][2]+=a2*b2;acc[2][3]+=a2*b3;
            acc[3][0]+=a3*b0;acc[3][1]+=a3*b1;acc[3][2]+=a3*b2;acc[3][3]+=a3*b3;
        }
        __syncthreads();
    }
    #pragma unroll
    for (int i = 0; i < 4; i++) {
        int r = row0 + ty*4 + i;
        #pragma unroll
        for (int j = 0; j < 4; j++) {
            int c = col0 + tx*4 + j;
            float v = acc[i][j];
            if (bias) v += bias[c];
            if (relu) v = fmaxf(v, 0.f);
            size_t o = (size_t)r*Nc + c;
            if (accum) C[o] += v; else C[o] = v;
        }
    }
}

__global__ void ln_kernel(const float* __restrict__ x, float* __restrict__ y)
{
    int row = blockIdx.x, t = threadIdx.x;
    const float* xr = x + (size_t)row*Dd;
    __shared__ float red[128];
    float a = xr[t], b = xr[t+128], c = xr[t+256];
    red[t] = a + b + c; __syncthreads();
    for (int o = 64; o > 0; o >>= 1) { if (t < o) red[t] += red[t+o]; __syncthreads(); }
    float m = red[0] / (float)Dd; __syncthreads();
    float da=a-m, db=b-m, dc=c-m;
    red[t] = da*da + db*db + dc*dc; __syncthreads();
    for (int o = 64; o > 0; o >>= 1) { if (t < o) red[t] += red[t+o]; __syncthreads(); }
    float inv = rsqrtf(red[0] / (float)Dd + 1e-5f);
    float* yr = y + (size_t)row*Dd;
    yr[t]=da*inv; yr[t+128]=db*inv; yr[t+256]=dc*inv;
}

// one block per (q,h,b); Sk<=128
__global__ void attn_kernel(const float* __restrict__ q, const float* __restrict__ kmat,
                            const float* __restrict__ vmat, const unsigned char* __restrict__ mask,
                            float* __restrict__ ctx, int Sq, int Sk)
{
    int qi = blockIdx.x, h = blockIdx.y, b = blockIdx.z, t = threadIdx.x;
    __shared__ float shq[DHh], shp[128], red[128];
    const float* qr = q + ((size_t)(b*Sq + qi))*Dd + h*DHh;
    if (t < DHh) shq[t] = qr[t];
    __syncthreads();
    float val = -3e38f;
    if (t < Sk) {
        const float* kr = kmat + ((size_t)(b*Sk + t))*Dd + h*DHh;
        float s = 0.f;
        #pragma unroll
        for (int d = 0; d < DHh; d++) s += shq[d]*kr[d];
        s /= sqrtf((float)DHh);
        if (mask && !mask[((size_t)b*Sq + qi)*Sk + t]) s = -1e9f;
        val = s;
    }
    red[t] = val; __syncthreads();
    for (int o = 64; o > 0; o >>= 1) { if (t < o) red[t] = fmaxf(red[t], red[t+o]); __syncthreads(); }
    float mx = red[0]; __syncthreads();
    float e = (t < Sk) ? expf(val - mx) : 0.f;
    shp[t] = e; red[t] = e; __syncthreads();
    for (int o = 64; o > 0; o >>= 1) { if (t < o) red[t] += red[t+o]; __syncthreads(); }
    float inv = 1.f / red[0];
    if (t < DHh) {
        float acc = 0.f;
        const float* vb = vmat + ((size_t)(b*Sk))*Dd + h*DHh + t;
        for (int kk = 0; kk < Sk; kk++) acc += shp[kk]*vb[(size_t)kk*Dd];
        ctx[((size_t)(b*Sq + qi))*Dd + h*DHh + t] = acc*inv;
    }
}

__global__ void fps_kernel(const float* __restrict__ pos, float* __restrict__ centers)
{
    int b = blockIdx.x, t = threadIdx.x;
    __shared__ float mind[Np];
    __shared__ float rv[512]; __shared__ int ri[512]; __shared__ float curp[3];
    const float* P = pos + (size_t)b*Np*3;
    float* C = centers + (size_t)b*Gg*3;
    if (t == 0) { curp[0]=P[0]; curp[1]=P[1]; curp[2]=P[2]; C[0]=P[0]; C[1]=P[1]; C[2]=P[2]; }
    __syncthreads();
    for (int i = t; i < Np; i += 512) {
        float dx=P[3*i]-curp[0], dy=P[3*i+1]-curp[1], dz=P[3*i+2]-curp[2];
        mind[i] = dx*dx + dy*dy + dz*dz;
    }
    __syncthreads();
    for (int s = 1; s < Gg; s++) {
        float bv = -3e38f; int bi = 0x7fffffff;
        for (int i = t; i < Np; i += 512) { float v = mind[i]; if (v > bv) { bv = v; bi = i; } }
        rv[t] = bv; ri[t] = bi; __syncthreads();
        for (int o = 256; o > 0; o >>= 1) {
            if (t < o && (rv[t+o] > rv[t] || (rv[t+o] == rv[t] && ri[t+o] < ri[t]))) { rv[t]=rv[t+o]; ri[t]=ri[t+o]; }
            __syncthreads();
        }
        if (t == 0) {
            int nxt = ri[0];
            curp[0]=P[3*nxt]; curp[1]=P[3*nxt+1]; curp[2]=P[3*nxt+2];
            C[3*s]=curp[0]; C[3*s+1]=curp[1]; C[3*s+2]=curp[2];
        }
        __syncthreads();
        for (int i = t; i < Np; i += 512) {
            float dx=P[3*i]-curp[0], dy=P[3*i+1]-curp[1], dz=P[3*i+2]-curp[2];
            float d = dx*dx + dy*dy + dz*dz;
            if (d < mind[i]) mind[i] = d;
        }
        __syncthreads();
    }
}

__global__ void knn_big_kernel(const float* __restrict__ qpts, const float* __restrict__ rpts,
                               int* __restrict__ nidx)
{
    int blk = blockIdx.x, b = blk / Gg, qc = blk % Gg, t = threadIdx.x;
    __shared__ float dist[Np];
    __shared__ float rv[128]; __shared__ int ri[128];
    const float* Q = qpts + ((size_t)b*Gg + qc)*3;
    float qx=Q[0], qy=Q[1], qz=Q[2], qq = qx*qx+qy*qy+qz*qz;
    const float* R = rpts + (size_t)b*Np*3;
    for (int i = t; i < Np; i += 128) {
        float rx=R[3*i], ry=R[3*i+1], rz=R[3*i+2];
        dist[i] = qq + (rx*rx+ry*ry+rz*rz) - 2.f*(qx*rx+qy*ry+qz*rz);
    }
    __syncthreads();
    for (int kk = 0; kk < Kk; kk++) {
        float bv = 3e38f; int bi = 0x7fffffff;
        for (int i = t; i < Np; i += 128) { float v = dist[i]; if (v < bv) { bv = v; bi = i; } }
        rv[t] = bv; ri[t] = bi; __syncthreads();
        for (int o = 64; o > 0; o >>= 1) {
            if (t < o && (rv[t+o] < rv[t] || (rv[t+o] == rv[t] && ri[t+o] < ri[t]))) { rv[t]=rv[t+o]; ri[t]=ri[t+o]; }
            __syncthreads();
        }
        if (t == 0) { nidx[((size_t)b*Gg + qc)*Kk + kk] = ri[0]; dist[ri[0]] = 3e38f; }
        __syncthreads();
    }
}

__global__ void knn_small_kernel(const float* __restrict__ pts, int S, int* __restrict__ nidx)
{
    int blk = blockIdx.x, b = blk / S, qi = blk % S, t = threadIdx.x;
    __shared__ float dist[128]; __shared__ float rv[128]; __shared__ int ri[128];
    const float* Q = pts + ((size_t)b*S + qi)*3;
    float qx=Q[0], qy=Q[1], qz=Q[2], qq=qx*qx+qy*qy+qz*qz;
    if (t < S) {
        const float* R = pts + ((size_t)b*S + t)*3;
        dist[t] = qq + (R[0]*R[0]+R[1]*R[1]+R[2]*R[2]) - 2.f*(qx*R[0]+qy*R[1]+qz*R[2]);
    } else dist[t] = 3e38f;
    __syncthreads();
    for (int kk = 0; kk < Kk; kk++) {
        rv[t] = dist[t]; ri[t] = t; __syncthreads();
        for (int o = 64; o > 0; o >>= 1) {
            if (t < o && (rv[t+o] < rv[t] || (rv[t+o] == rv[t] && ri[t+o] < ri[t]))) { rv[t]=rv[t+o]; ri[t]=ri[t+o]; }
            __syncthreads();
        }
        if (t == 0) { nidx[((size_t)b*S + qi)*Kk + kk] = ri[0]; dist[ri[0]] = 3e38f; }
        __syncthreads();
    }
}

__global__ void zero_u8_kernel(unsigned char* m, int n)
{ int i = blockIdx.x*blockDim.x + threadIdx.x; if (i < n) m[i] = 0; }

__global__ void scatter_mask_kernel(const int* __restrict__ nidx, unsigned char* __restrict__ m, int S)
{
    int i = blockIdx.x*blockDim.x + threadIdx.x;
    if (i >= Bb*S*Kk) return;
    int b = i / (S*Kk), r = (i / Kk) % S;
    m[((size_t)b*S + r)*S + nidx[i]] = 1;
}

__global__ void group_rel_kernel(const float* __restrict__ pos, const float* __restrict__ centers,
                                 const int* __restrict__ nidx, float* __restrict__ rel)
{
    int i = blockIdx.x*blockDim.x + threadIdx.x;
    if (i >= Bb*Gg*Kk) return;
    int b = i / (Gg*Kk), g = (i / Kk) % Gg, src = nidx[i];
    const float* P = pos + ((size_t)b*Np + src)*3;
    const float* C = centers + ((size_t)b*Gg + g)*3;
    rel[3*i]=P[0]-C[0]; rel[3*i+1]=P[1]-C[1]; rel[3*i+2]=P[2]-C[2];
}

__global__ void gmax_kernel(const float* __restrict__ f, float* __restrict__ g, int C)
{
    int i = blockIdx.x*blockDim.x + threadIdx.x;
    if (i >= Bb*Gg*C) return;
    int bg = i / C, c = i % C;
    const float* fp = f + (size_t)bg*Kk*C + c;
    float m = fp[0];
    #pragma unroll
    for (int k = 1; k < Kk; k++) m = fmaxf(m, fp[(size_t)k*C]);
    g[i] = m;
}

__global__ void cat_kernel(const float* __restrict__ g, const float* __restrict__ f, float* __restrict__ cat)
{
    int i = blockIdx.x*blockDim.x + threadIdx.x;
    if (i >= Bb*Gg*Kk*512) return;
    int c = i % 512, r = i / 512, bg = r / Kk;
    cat[i] = (c < 256) ? g[(size_t)bg*256 + c] : f[(size_t)r*256 + (c - 256)];
}

__global__ void pe_kernel(const float* __restrict__ xyz, float* __restrict__ pe, int rows)
{
    int i = blockIdx.x*blockDim.x + threadIdx.x;
    if (i >= rows*Dd) return;
    int r = i / Dd, j = i % Dd, c = j / 128, jj = j % 128;
    float x = xyz[(size_t)r*3 + c];
    float dt = powf(10000.0f, (float)(2*(jj/2)) / 128.0f);
    float p = x / dt;
    pe[i] = (jj & 1) ? cosf(p) : sinf(p);
}

__global__ void gather_kernel(const float* __restrict__ src, const int* __restrict__ idx,
                              float* __restrict__ dst, int outR, int inR, int W)
{
    int row = blockIdx.x, b = row / outR, r = row % outR;
    int s = idx[(size_t)b*outR + r];
    const float* sp = src + ((size_t)b*inR + s)*W;
    float* dp = dst + (size_t)row*W;
    for (int w = threadIdx.x; w < W; w += blockDim.x) dp[w] = sp[w];
}

__global__ void decq_kernel(const float* __restrict__ visout, const float* __restrict__ cpe,
                            const float* __restrict__ mask_token, const int* __restrict__ mskidx,
                            const int* __restrict__ visidx, float* __restrict__ x)
{
    int i = blockIdx.x*blockDim.x + threadIdx.x;
    if (i >= Bb*(Mm+Vv)*Dd) return;
    int d = i % Dd, r = (i / Dd) % (Mm+Vv), b = i / (Dd*(Mm+Vv));
    float base; int pidx;
    if (r < Mm) { base = mask_token[d]; pidx = mskidx[(size_t)b*Mm + r]; }
    else { base = visout[((size_t)b*Vv + (r-Mm))*Dd + d]; pidx = visidx[(size_t)b*Vv + (r-Mm)]; }
    x[i] = base + cpe[((size_t)b*Gg + pidx)*Dd + d];
}

__global__ void add_kernel(const float* __restrict__ a, const float* __restrict__ b,
                           float* __restrict__ c, int n)
{ int i = blockIdx.x*blockDim.x + threadIdx.x; if (i < n) c[i] = a[i] + b[i]; }

__global__ void nn3_kernel(const float* __restrict__ pos, const float* __restrict__ centers,
                           int* __restrict__ oi, float* __restrict__ ow)
{
    int i = blockIdx.x*blockDim.x + threadIdx.x;
    if (i >= Bb*Np) return;
    int b = i / Np;
    const float* P = pos + (size_t)i*3;
    float px=P[0], py=P[1], pz=P[2], qq=px*px+py*py+pz*pz;
    float d0=3e38f, d1=3e38f, d2=3e38f; int i0=-1, i1=-1, i2=-1;
    const float* C = centers + (size_t)b*Gg*3;
    for (int g = 0; g < Gg; g++) {
        float cx=C[3*g], cy=C[3*g+1], cz=C[3*g+2];
        float d = qq + (cx*cx+cy*cy+cz*cz) - 2.f*(px*cx+py*cy+pz*cz);
        if (d < d0) { d2=d1;i2=i1; d1=d0;i1=i0; d0=d;i0=g; }
        else if (d < d1) { d2=d1;i2=i1; d1=d;i1=g; }
        else if (d < d2) { d2=d;i2=g; }
    }
    float w0=1.f/(fmaxf(d0,0.f)+1e-8f), w1=1.f/(fmaxf(d1,0.f)+1e-8f), w2=1.f/(fmaxf(d2,0.f)+1e-8f);
    float s = w0+w1+w2;
    ow[3*i]=w0/s; ow[3*i+1]=w1/s; ow[3*i+2]=w2/s;
    oi[3*i]=i0; oi[3*i+1]=i1; oi[3*i+2]=i2;
}

__global__ void upcat_kernel(const float* __restrict__ feats, const float* __restrict__ pos,
                             const int* __restrict__ oi, const float* __restrict__ ow,
                             float* __restrict__ cat)
{
    int row = blockIdx.x, b = row / Np, t = threadIdx.x;
    int i0=oi[3*row], i1=oi[3*row+1], i2=oi[3*row+2];
    float w0=ow[3*row], w1=ow[3*row+1], w2=ow[3*row+2];
    const float* F = feats + (size_t)b*Gg*Dd;
    float* cp = cat + (size_t)row*387;
    for (int d = t; d < Dd; d += 128)
        cp[d] = w0*F[(size_t)i0*Dd+d] + w1*F[(size_t)i1*Dd+d] + w2*F[(size_t)i2*Dd+d];
    if (t < 3) cp[Dd + t] = pos[(size_t)row*3 + t];
}

__global__ void loss_kernel(const float* __restrict__ fullout, const int* __restrict__ mskidx,
                            const float* __restrict__ decx, float* __restrict__ partial)
{
    __shared__ float red[256];
    int t = threadIdx.x;
    float acc = 0.f;
    for (int i = blockIdx.x*256 + t; i < Bb*Mm*Dd; i += 64*256) {
        int d = i % Dd, r = (i / Dd) % Mm, b = i / (Dd*Mm);
        int gi = mskidx[(size_t)b*Mm + r];
        float tv = fullout[((size_t)b*Gg + gi)*Dd + d];
        float pv = decx[((size_t)b*(Mm+Vv) + r)*Dd + d];
        float a = fabsf(pv - tv);
        acc += (a < 2.0f) ? 0.25f*a*a : a - 1.0f;
    }
    red[t] = acc; __syncthreads();
    for (int o = 128; o > 0; o >>= 1) { if (t < o) red[t] += red[t+o]; __syncthreads(); }
    if (t == 0) partial[blockIdx.x] = red[0];
}

__global__ void loss_final_kernel(const float* __restrict__ pa, const float* __restrict__ pb,
                                  float* __restrict__ out)
{
    float sa = 0.f, sb = 0.f;
    for (int i = 0; i < 64; i++) { sa += pa[i]; sb += pb[i]; }
    float cnt = (float)(Bb*Mm*Dd);
    out[0] = 0.5f*(sa/cnt) + 0.5f*(sb/cnt);
}

__global__ void copy_kernel(const float* __restrict__ a, float* __restrict__ b, int n)
{ int i = blockIdx.x*blockDim.x + threadIdx.x; if (i < n) b[i] = a[i]; }

static void gemm(const float* A, const float* W, const float* bias, float* C,
                 int rows, int Kd, int Nc, int relu, int accum)
{
    dim3 grid(Nc/64, rows/64);
    gemm_kernel<<<grid, 256>>>(A, W, bias, C, rows, Kd, Nc, relu, accum);
}

static void attn_block(const float* lnq, const float* lnkv, const float* w,
                       const unsigned char* mask, float* x, int Sq, int Sk,
                       float* qb, float* kb, float* vb, float* cb)
{
    gemm(lnq,  w,           nullptr, qb, Bb*Sq, Dd, Dd, 0, 0);
    gemm(lnkv, w + Dd*Dd,   nullptr, kb, Bb*Sk, Dd, Dd, 0, 0);
    gemm(lnkv, w + 2*Dd*Dd, nullptr, vb, Bb*Sk, Dd, Dd, 0, 0);
    dim3 g(Sq, NHh, Bb);
    attn_kernel<<<g, 128>>>(qb, kb, vb, mask, cb, Sq, Sk);
    gemm(cb, w + 3*Dd*Dd, nullptr, x, Bb*Sq, Dd, Dd, 0, 1);
}

static void encode_pair(float* Sb, float* Tb, const unsigned char* mS, const unsigned char* mT,
                        int S, const float* cxw, const float* ff1, const float* ff2,
                        float* lnS, float* lnT, float* qb, float* kb, float* vb, float* cb, float* hid)
{
    int rows = Bb*S;
    const float* sa = cxw;
    const float* ca = cxw + 4*Dd*Dd;
    ln_kernel<<<rows, 128>>>(Sb, lnS);
    attn_block(lnS, lnS, sa, mS, Sb, S, S, qb, kb, vb, cb);
    ln_kernel<<<rows, 128>>>(Tb, lnT);
    attn_block(lnT, lnT, sa, mT, Tb, S, S, qb, kb, vb, cb);
    ln_kernel<<<rows, 128>>>(Sb, lnS);
    ln_kernel<<<rows, 128>>>(Tb, lnT);
    attn_block(lnS, lnT, ca, nullptr, Sb, S, S, qb, kb, vb, cb);
    attn_block(lnT, lnS, ca, nullptr, Tb, S, S, qb, kb, vb, cb);
    ln_kernel<<<rows, 128>>>(Sb, lnS);
    gemm(lnS, ff1, nullptr, hid, rows, Dd, FFf, 1, 0);
    gemm(hid, ff2, nullptr, Sb, rows, FFf, Dd, 0, 1);
    ln_kernel<<<rows, 128>>>(Tb, lnT);
    gemm(lnT, ff1, nullptr, hid, rows, Dd, FFf, 1, 0);
    gemm(hid, ff2, nullptr, Tb, rows, FFf, Dd, 0, 1);
}

#define GETSYM(var, sym) do { void* _p; cudaGetSymbolAddress(&_p, sym); var = (decltype(var))_p; } while (0)

extern "C" void kernel_launch(void* const* d_in, const int* in_sizes, int n_in,
                              void* d_out_v, int out_size)
{
    (void)in_sizes; (void)n_in; (void)out_size;
    const float* pos[2]    = {(const float*)d_in[0], (const float*)d_in[1]};
    const int*   visidx[2] = {(const int*)d_in[2], (const int*)d_in[4]};
    const int*   mskidx[2] = {(const int*)d_in[3], (const int*)d_in[5]};
    const float* tok_w1 = (const float*)d_in[6];  const float* tok_b1 = (const float*)d_in[7];
    const float* tok_w2 = (const float*)d_in[8];  const float* tok_b2 = (const float*)d_in[9];
    const float* tok_w3 = (const float*)d_in[10]; const float* tok_b3 = (const float*)d_in[11];
    const float* tok_w4 = (const float*)d_in[12]; const float* tok_b4 = (const float*)d_in[13];
    const float* mask_token = (const float*)d_in[14];
    const float* cx_attn = (const float*)d_in[15];
    const float* cx_ff1  = (const float*)d_in[16]; const float* cx_ff2 = (const float*)d_in[17];
    const float* enc_sa  = (const float*)d_in[18]; const float* enc_ca = (const float*)d_in[19];
    const float* enc_ff1 = (const float*)d_in[20]; const float* enc_ff2 = (const float*)d_in[21];
    const float* dec_ca  = (const float*)d_in[22]; const float* dec_ff1 = (const float*)d_in[23];
    const float* dec_ff2 = (const float*)d_in[24];
    const float* up_w1 = (const float*)d_in[25]; const float* up_b1 = (const float*)d_in[26];
    const float* up_w2 = (const float*)d_in[27]; const float* up_b2 = (const float*)d_in[28];
    float* dout = (float*)d_out_v;

    float *centersB, *relB, *f1B, *f2B, *gmaxB, *catB, *t1B, *t2B, *tokensB;
    float *cpeB, *ppeB, *vis3B, *visB, *fullB, *decxB, *mbufB, *lnmB, *lnSB, *lnTB;
    float *lnbigB, *qB, *kB, *vB, *ctxB, *hidB, *upcatB, *nn3wB, *lpartB;
    int *nidxB, *nidxSB, *nn3iB;
    unsigned char *mfullB, *mvisB;
    GETSYM(centersB, g_centers); GETSYM(nidxB, g_nidx); GETSYM(nidxSB, g_nidxS);
    GETSYM(relB, g_rel); GETSYM(f1B, g_f1); GETSYM(f2B, g_f2); GETSYM(gmaxB, g_gmax);
    GETSYM(catB, g_cat); GETSYM(t1B, g_t1); GETSYM(t2B, g_t2); GETSYM(tokensB, g_tokens);
    GETSYM(cpeB, g_cpe); GETSYM(ppeB, g_ppe); GETSYM(mfullB, g_mfull); GETSYM(mvisB, g_mvis);
    GETSYM(vis3B, g_vis3); GETSYM(visB, g_visbuf); GETSYM(fullB, g_fullbuf); GETSYM(decxB, g_decx);
    GETSYM(mbufB, g_mbuf); GETSYM(lnmB, g_lnm); GETSYM(lnSB, g_lnS); GETSYM(lnTB, g_lnT);
    GETSYM(lnbigB, g_lnbig); GETSYM(qB, g_qbuf); GETSYM(kB, g_kbuf); GETSYM(vB, g_vbuf);
    GETSYM(ctxB, g_ctx); GETSYM(hidB, g_hid); GETSYM(upcatB, g_upcat);
    GETSYM(nn3iB, g_nn3i); GETSYM(nn3wB, g_nn3w); GETSYM(lpartB, g_lpart);

    float* centers[2] = {centersB, centersB + Bb*Gg*3};
    float* tokens[2]  = {tokensB,  tokensB  + Bb*Gg*Dd};
    float* cpe[2]     = {cpeB,     cpeB     + Bb*Gg*Dd};
    float* ppe[2]     = {ppeB,     ppeB     + Bb*Np*Dd};
    float* visb[2]    = {visB,     visB     + Bb*Vv*Dd};
    float* fullb[2]   = {fullB,    fullB    + Bb*Gg*Dd};
    float* decx[2]    = {decxB,    decxB    + Bb*(Mm+Vv)*Dd};
    unsigned char* mfull[2] = {mfullB, mfullB + Bb*Gg*Gg};
    unsigned char* mvis[2]  = {mvisB,  mvisB  + Bb*Vv*Vv};

    // Phase 1: tokenize + PE + masks
    for (int s = 0; s < 2; s++) {
        fps_kernel<<<Bb, 512>>>(pos[s], centers[s]);
        knn_big_kernel<<<Bb*Gg, 128>>>(centers[s], pos[s], nidxB);
        group_rel_kernel<<<(Bb*Gg*Kk + 255)/256, 256>>>(pos[s], centers[s], nidxB, relB);
        gemm(relB, tok_w1, tok_b1, f1B, Bb*Gg*Kk, 3, 128, 1, 0);
        gemm(f1B, tok_w2, tok_b2, f2B, Bb*Gg*Kk, 128, 256, 0, 0);
        gmax_kernel<<<(Bb*Gg*256 + 255)/256, 256>>>(f2B, gmaxB, 256);
        cat_kernel<<<(Bb*Gg*Kk*512 + 255)/256, 256>>>(gmaxB, f2B, catB);
        gemm(catB, tok_w3, tok_b3, t1B, Bb*Gg*Kk, 512, 512, 1, 0);
        gemm(t1B, tok_w4, tok_b4, t2B, Bb*Gg*Kk, 512, Dd, 0, 0);
        gmax_kernel<<<(Bb*Gg*Dd + 255)/256, 256>>>(t2B, tokens[s], Dd);
        pe_kernel<<<(Bb*Gg*Dd + 255)/256, 256>>>(centers[s], cpe[s], Bb*Gg);
        pe_kernel<<<(Bb*Np*Dd + 255)/256, 256>>>(pos[s], ppe[s], Bb*Np);
        knn_small_kernel<<<Bb*Gg, 128>>>(centers[s], Gg, nidxSB);
        zero_u8_kernel<<<(Bb*Gg*Gg + 255)/256, 256>>>(mfull[s], Bb*Gg*Gg);
        scatter_mask_kernel<<<(Bb*Gg*Kk + 255)/256, 256>>>(nidxSB, mfull[s], Gg);
        gather_kernel<<<Bb*Vv, 32>>>(centers[s], visidx[s], vis3B, Vv, Gg, 3);
        knn_small_kernel<<<Bb*Vv, 128>>>(vis3B, Vv, nidxSB);
        zero_u8_kernel<<<(Bb*Vv*Vv + 255)/256, 256>>>(mvis[s], Bb*Vv*Vv);
        scatter_mask_kernel<<<(Bb*Vv*Kk + 255)/256, 256>>>(nidxSB, mvis[s], Vv);
        gather_kernel<<<Bb*Vv, 128>>>(tokens[s], visidx[s], visb[s], Vv, Gg, Dd);
        copy_kernel<<<(Bb*Gg*Dd + 255)/256, 256>>>(tokens[s], fullb[s], Bb*Gg*Dd);
    }

    // Phase 2: cross encoders
    encode_pair(visb[0], visb[1], mvis[0], mvis[1], Vv, cx_attn, cx_ff1, cx_ff2,
                lnSB, lnTB, qB, kB, vB, ctxB, hidB);
    encode_pair(fullb[0], fullb[1], mfull[0], mfull[1], Gg, cx_attn, cx_ff1, cx_ff2,
                lnSB, lnTB, qB, kB, vB, ctxB, hidB);

    // Phase 3: MAE decoder + loss
    for (int s = 0; s < 2; s++) {
        int o = 1 - s;
        decq_kernel<<<(Bb*(Mm+Vv)*Dd + 255)/256, 256>>>(visb[s], cpe[s], mask_token,
                                                        mskidx[s], visidx[s], decx[s]);
        add_kernel<<<(Bb*Gg*Dd + 255)/256, 256>>>(fullb[o], cpe[o], mbufB, Bb*Gg*Dd);
        ln_kernel<<<Bb*Gg, 128>>>(mbufB, lnmB);
        for (int l = 0; l < 4; l++) {
            const float* sal = enc_sa + (size_t)l*4*Dd*Dd;
            const float* cal = enc_ca + (size_t)l*4*Dd*Dd;
            ln_kernel<<<Bb*(Mm+Vv), 128>>>(decx[s], lnSB);
            attn_block(lnSB, lnSB, sal, nullptr, decx[s], Mm+Vv, Mm+Vv, qB, kB, vB, ctxB);
            ln_kernel<<<Bb*(Mm+Vv), 128>>>(decx[s], lnSB);
            attn_block(lnSB, lnmB, cal, nullptr, decx[s], Mm+Vv, Gg, qB, kB, vB, ctxB);
            ln_kernel<<<Bb*(Mm+Vv), 128>>>(decx[s], lnSB);
            gemm(lnSB, enc_ff1 + (size_t)l*Dd*FFf, nullptr, hidB, Bb*(Mm+Vv), Dd, FFf, 1, 0);
            gemm(hidB, enc_ff2 + (size_t)l*FFf*Dd, nullptr, decx[s], Bb*(Mm+Vv), FFf, Dd, 0, 1);
        }
        loss_kernel<<<64, 256>>>(fullb[s], mskidx[s], decx[s], lpartB + s*64);
    }

    // Phase 4: upsample + dense decoder
    for (int s = 0; s < 2; s++) {
        float* X = dout + (size_t)s*Bb*Np*Dd;
        nn3_kernel<<<(Bb*Np + 255)/256, 256>>>(pos[s], centers[s], nn3iB, nn3wB);
        upcat_kernel<<<Bb*Np, 128>>>(fullb[s], pos[s], nn3iB, nn3wB, upcatB);
        gemm(upcatB, up_w1, up_b1, lnbigB, Bb*Np, 387, Dd, 1, 0);
        gemm(lnbigB, up_w2, up_b2, ctxB, Bb*Np, Dd, Dd, 1, 0);
        add_kernel<<<(Bb*Np*Dd + 255)/256, 256>>>(ctxB, ppe[s], X, Bb*Np*Dd);
        add_kernel<<<(Bb*Gg*Dd + 255)/256, 256>>>(fullb[s], cpe[s], mbufB, Bb*Gg*Dd);
        ln_kernel<<<Bb*Gg, 128>>>(mbufB, lnmB);
        for (int l = 0; l < 2; l++) {
            const float* cal = dec_ca + (size_t)l*4*Dd*Dd;
            ln_kernel<<<Bb*Np, 128>>>(X, lnbigB);
            attn_block(lnbigB, lnmB, cal, nullptr, X, Np, Gg, qB, kB, vB, ctxB);
            ln_kernel<<<Bb*Np, 128>>>(X, lnbigB);
            gemm(lnbigB, dec_ff1 + (size_t)l*Dd*FFf, nullptr, hidB, Bb*Np, Dd, FFf, 1, 0);
            gemm(hidB, dec_ff2 + (size_t)l*FFf*Dd, nullptr, X, Bb*Np, FFf, Dd, 0, 1);
        }
    }
    loss_final_kernel<<<1, 1>>>(lpartB, lpartB + 64, dout + (size_t)2*Bb*Np*Dd);
}